// round 2
// baseline (speedup 1.0000x reference)
#include <cuda_runtime.h>

#define BATCH 512
#define NPTS  64
#define KNBR  16
#define BNTOT 32768
#define NEDGE 524288
#define EPSV  1e-5f

__device__ float g_h0[BNTOT*64];
__device__ float g_h1[BNTOT*64];
__device__ float g_h2[BNTOT*128];
__device__ float g_h3[BNTOT*256];
__device__ float g_p [BNTOT*256];
__device__ float g_q [BNTOT*256];
__device__ float g_wd[256*256];
__device__ int   g_idx[NEDGE];
__device__ float g_maxraw[BNTOT*256];
__device__ float g_sum[512];
__device__ float g_sumsq[512];
__device__ float g_scale[512];
__device__ float g_shift[512];
__device__ float g_pooled[BATCH*896];
__device__ float g_z1[BATCH*512];
__device__ float g_z2[BATCH*256];

__device__ __forceinline__ void atomicMaxFloat(float* addr, float v) {
    if (v >= 0.f) atomicMax((int*)addr, __float_as_int(v));
    else          atomicMin((unsigned int*)addr, __float_as_uint(v));
}

// ---- generic fp32 GEMM: C[M,N] = A[M,K] @ W[K,N]; M%64==0, N%64==0 ----
__global__ __launch_bounds__(256) void k_gemm(
    const float* __restrict__ A, const float* __restrict__ W,
    float* __restrict__ Cc, int M, int Kd, int N)
{
    __shared__ float As[16][65];
    __shared__ float Ws[16][64];
    const int tid = threadIdx.x;
    const int row0 = blockIdx.y * 64, col0 = blockIdx.x * 64;
    const int ty = tid >> 4, tx = tid & 15;
    const int lkt = tid & 15, lrm = tid >> 4;
    const int wcn = tid & 63, wkt = tid >> 6;
    float acc[4][4];
#pragma unroll
    for (int r = 0; r < 4; r++)
#pragma unroll
        for (int c = 0; c < 4; c++) acc[r][c] = 0.f;

    for (int k0 = 0; k0 < Kd; k0 += 16) {
#pragma unroll
        for (int s = 0; s < 4; s++) {
            int kk = k0 + lkt;
            As[lkt][lrm + 16*s] = (kk < Kd) ? A[(size_t)(row0 + lrm + 16*s) * Kd + kk] : 0.f;
        }
#pragma unroll
        for (int s = 0; s < 4; s++) {
            int kk = k0 + wkt + 4*s;
            Ws[wkt + 4*s][wcn] = (kk < Kd) ? W[(size_t)kk * N + col0 + wcn] : 0.f;
        }
        __syncthreads();
#pragma unroll
        for (int kk = 0; kk < 16; kk++) {
            float a0 = As[kk][ty*4+0], a1 = As[kk][ty*4+1];
            float a2 = As[kk][ty*4+2], a3 = As[kk][ty*4+3];
            float4 bv = *(const float4*)&Ws[kk][tx*4];
#pragma unroll
            for (int r = 0; r < 4; r++) {
                float a = (r==0)?a0:(r==1)?a1:(r==2)?a2:a3;
                acc[r][0] = fmaf(a, bv.x, acc[r][0]);
                acc[r][1] = fmaf(a, bv.y, acc[r][1]);
                acc[r][2] = fmaf(a, bv.z, acc[r][2]);
                acc[r][3] = fmaf(a, bv.w, acc[r][3]);
            }
        }
        __syncthreads();
    }
#pragma unroll
    for (int r = 0; r < 4; r++)
#pragma unroll
        for (int c = 0; c < 4; c++)
            Cc[(size_t)(row0 + ty*4 + r) * N + col0 + tx*4 + c] = acc[r][c];
}

// ---- kNN: per-batch 64x64 distances, 16 nearest (excluding self) ----
template<int C>
__global__ void k_knn(const float* __restrict__ x)
{
    extern __shared__ float s[];
    float* xs = s;
    float* ds = s + NPTS * (C + 1);
    const int b = blockIdx.x;
    for (int i = threadIdx.x; i < NPTS * C; i += 64) {
        int n = i / C, c = i - n * C;
        xs[n * (C + 1) + c] = x[(size_t)(b * NPTS + n) * C + c];
    }
    __syncthreads();
    const int n = threadIdx.x;
    for (int m = 0; m < NPTS; m++) {
        float acc = 0.f;
#pragma unroll 8
        for (int c = 0; c < C; c++) {
            float d = xs[n * (C + 1) + c] - xs[m * (C + 1) + c];
            acc = fmaf(d, d, acc);
        }
        ds[n * 65 + m] = acc;
    }
    for (int sIt = 0; sIt < KNBR + 1; sIt++) {
        float best = 3.4e38f; int bi = 0;
        for (int m = 0; m < NPTS; m++) {
            float v = ds[n * 65 + m];
            if (v < best) { best = v; bi = m; }
        }
        ds[n * 65 + bi] = 3.4e38f;
        if (sIt > 0) g_idx[(b * NPTS + n) * KNBR + sIt - 1] = bi;
    }
}

__global__ void k_wdiff(const float* __restrict__ w1, int C, int C1)
{
    int i = blockIdx.x * blockDim.x + threadIdx.x;
    if (i < C * C1) g_wd[i] = w1[i] - w1[C * C1 + i];
}

__global__ void k_zero_stats()
{
    g_sum[threadIdx.x] = 0.f; g_sumsq[threadIdx.x] = 0.f;
}

__global__ void k_colstats(const float* __restrict__ X, int M, int Ncol, int rpb)
{
    int c = threadIdx.x;
    int r0 = blockIdx.x * rpb;
    int r1 = min(r0 + rpb, M);
    float s = 0.f, s2 = 0.f;
    for (int r = r0; r < r1; r++) {
        float v = X[(size_t)r * Ncol + c];
        s += v; s2 = fmaf(v, v, s2);
    }
    atomicAdd(&g_sum[c], s);
    atomicAdd(&g_sumsq[c], s2);
}

// bn1 stats over edges of t = p[n] + q[idx[n,k]]
__global__ void k_edgestats(const float* __restrict__ p, const float* __restrict__ q, int C1)
{
    const int b = blockIdx.x;
    const int c = threadIdx.x;
    __shared__ int idxs[NPTS * KNBR];
    for (int i = threadIdx.x; i < NPTS * KNBR; i += blockDim.x)
        idxs[i] = g_idx[b * NPTS * KNBR + i];
    __syncthreads();
    float s = 0.f, s2 = 0.f;
    for (int n = 0; n < NPTS; n++) {
        float pv = p[(size_t)(b * NPTS + n) * C1 + c];
#pragma unroll
        for (int k = 0; k < KNBR; k++) {
            int j = idxs[n * KNBR + k];
            float v = pv + q[(size_t)(b * NPTS + j) * C1 + c];
            s += v; s2 = fmaf(v, v, s2);
        }
    }
    atomicAdd(&g_sum[c], s);
    atomicAdd(&g_sumsq[c], s2);
}

__global__ void k_finalize(const float* __restrict__ g, const float* __restrict__ bb,
                           int C, float invcnt)
{
    int c = threadIdx.x;
    if (c < C) {
        float m  = g_sum[c] * invcnt;
        float vv = g_sumsq[c] * invcnt - m * m;
        float sc = g[c] * rsqrtf(vv + EPSV);
        g_scale[c] = sc;
        g_shift[c] = bb[c] - m * sc;
    }
}

__global__ void k_bnlrelu(const float* __restrict__ X, float* __restrict__ Y,
                          int total, int mask)
{
    int i = blockIdx.x * blockDim.x + threadIdx.x;
    if (i < total) {
        int c = i & mask;
        float v = fmaf(X[i], g_scale[c], g_shift[c]);
        Y[i] = fmaxf(v, 0.2f * v);
    }
}

__global__ void k_maxfix(const float* __restrict__ raw, float* __restrict__ Y,
                         int total, int mask)
{
    int i = blockIdx.x * blockDim.x + threadIdx.x;
    if (i < total) {
        float v = raw[i];
        if (v < -3.0e38f) Y[i] = 0.f;
        else {
            int c = i & mask;
            float t = fmaf(v, g_scale[c], g_shift[c]);
            Y[i] = fmaxf(t, 0.2f * t);
        }
    }
}

// ---- fused per-edge GEMM2 + bn2 stats + scatter-max ----
// grid (BATCH, C2/64), block 256. One block: all 1024 edges of batch b,
// 64 output channels [cb, cb+64).
template<int C1>
__global__ __launch_bounds__(256, 1) void k_gemm2(
    const float* __restrict__ p, const float* __restrict__ q,
    const float* __restrict__ w2, int C2, float* __restrict__ omg)
{
    extern __shared__ float sm[];
    constexpr int PS = C1 + 1;
    float* p_s  = sm;
    float* q_s  = p_s + NPTS * PS;
    float* w_s  = q_s + NPTS * PS;
    float* om   = w_s + C1 * 64;
    float* ssum = om + 64 * 65;
    float* ssq  = ssum + 64;
    int*   idxs = (int*)(ssq + 64);

    const int b = blockIdx.x, cb = blockIdx.y * 64;
    const int tid = threadIdx.x;

    for (int i = tid; i < NPTS * C1; i += 256) {
        int n = i / C1, c = i - n * C1;
        float sc = g_scale[c], sh = g_shift[c];
        p_s[n * PS + c] = fmaf(p[(size_t)(b * NPTS + n) * C1 + c], sc, sh);
        q_s[n * PS + c] = q[(size_t)(b * NPTS + n) * C1 + c] * sc;
    }
    for (int i = tid; i < C1 * 64; i += 256) {
        int k = i >> 6, c = i & 63;
        w_s[i] = w2[(size_t)k * C2 + cb + c];
    }
    for (int i = tid; i < NPTS * KNBR; i += 256) idxs[i] = g_idx[b * NPTS * KNBR + i];
    const float NEGINF = __int_as_float(0xff800000);
    for (int i = tid; i < 64 * 65; i += 256) om[i] = NEGINF;
    if (tid < 64) { ssum[tid] = 0.f; ssq[tid] = 0.f; }
    __syncthreads();

    const int cs = tid & 3;
    const int es = tid >> 2;
    const int cOff = cs * 16;
    float lsum[16], lsq[16];
#pragma unroll
    for (int c = 0; c < 16; c++) { lsum[c] = 0.f; lsq[c] = 0.f; }

#pragma unroll 1
    for (int pass = 0; pass < 4; pass++) {
        const int e0 = pass * 256 + es * 4;
        const int n = e0 >> 4;
        const int j0 = idxs[e0], j1 = idxs[e0+1], j2 = idxs[e0+2], j3 = idxs[e0+3];
        const float* pr = p_s + n * PS;
        const float* qa = q_s + j0 * PS;
        const float* qb = q_s + j1 * PS;
        const float* qc = q_s + j2 * PS;
        const float* qd = q_s + j3 * PS;
        float acc[4][16];
#pragma unroll
        for (int v = 0; v < 4; v++)
#pragma unroll
            for (int c = 0; c < 16; c++) acc[v][c] = 0.f;

#pragma unroll 4
        for (int i = 0; i < C1; i++) {
            float pv = pr[i];
            float h0 = pv + qa[i]; h0 = fmaxf(h0, 0.2f * h0);
            float h1 = pv + qb[i]; h1 = fmaxf(h1, 0.2f * h1);
            float h2 = pv + qc[i]; h2 = fmaxf(h2, 0.2f * h2);
            float h3 = pv + qd[i]; h3 = fmaxf(h3, 0.2f * h3);
            const float4* wr = (const float4*)(w_s + i * 64 + cOff);
            float4 w0 = wr[0], w1 = wr[1], w2v = wr[2], w3 = wr[3];
            float wv[16];
            *(float4*)&wv[0]  = w0; *(float4*)&wv[4]  = w1;
            *(float4*)&wv[8]  = w2v; *(float4*)&wv[12] = w3;
#pragma unroll
            for (int c = 0; c < 16; c++) {
                acc[0][c] = fmaf(h0, wv[c], acc[0][c]);
                acc[1][c] = fmaf(h1, wv[c], acc[1][c]);
                acc[2][c] = fmaf(h2, wv[c], acc[2][c]);
                acc[3][c] = fmaf(h3, wv[c], acc[3][c]);
            }
        }
#pragma unroll
        for (int v = 0; v < 4; v++) {
            int j = (v==0)?j0:(v==1)?j1:(v==2)?j2:j3;
            float* obase = om + j * 65 + cOff;
#pragma unroll
            for (int c = 0; c < 16; c++) {
                float y = acc[v][c];
                lsum[c] += y;
                lsq[c] = fmaf(y, y, lsq[c]);
                if (y > obase[c]) atomicMaxFloat(&obase[c], y);
            }
        }
    }
#pragma unroll
    for (int c = 0; c < 16; c++) {
        atomicAdd(&ssum[cOff + c], lsum[c]);
        atomicAdd(&ssq[cOff + c],  lsq[c]);
    }
    __syncthreads();
    if (tid < 64) {
        atomicAdd(&g_sum[cb + tid], ssum[tid]);
        atomicAdd(&g_sumsq[cb + tid], ssq[tid]);
    }
    for (int i = tid; i < NPTS * 64; i += 256) {
        int jj = i >> 6, c = i & 63;
        omg[(size_t)(b * NPTS + jj) * C2 + cb + c] = om[jj * 65 + c];
    }
}

__global__ void k_pool()
{
    const int b = blockIdx.x;
    const int c = threadIdx.x;   // 448
    const float* src; int cc, Cs;
    if (c < 64)       { src = g_h1; cc = c;       Cs = 64; }
    else if (c < 192) { src = g_h2; cc = c - 64;  Cs = 128; }
    else              { src = g_h3; cc = c - 192; Cs = 256; }
    float s = 0.f, mx = -3.4e38f;
    for (int n = 0; n < NPTS; n++) {
        float v = src[(size_t)(b * NPTS + n) * Cs + cc];
        s += v; mx = fmaxf(mx, v);
    }
    g_pooled[b * 896 + c]       = s * (1.f / 64.f);
    g_pooled[b * 896 + 448 + c] = mx;
}

__global__ void k_head_final(const float* __restrict__ wc3, const float* __restrict__ bc3,
                             float* __restrict__ out)
{
    int i = blockIdx.x * blockDim.x + threadIdx.x;
    if (i < BATCH * 2) {
        int bb = i >> 1, o = i & 1;
        float s = 0.f;
#pragma unroll 8
        for (int c = 0; c < 256; c++)
            s = fmaf(g_z2[bb * 256 + c], wc3[c * 2 + o], s);
        out[i] = s + bc3[o];
    }
}

// ---------------- host side ----------------
static size_t gemm2_smem(int C1) {
    return (size_t)(2 * NPTS * (C1 + 1) + C1 * 64 + 64 * 65 + 128 + NPTS * KNBR) * 4;
}

static void run_conv(const float* xin, int C,
                     const float* w1, const float* g1, const float* b1,
                     const float* w2, const float* g2, const float* b2,
                     float* outh, int C1, int C2,
                     float* p, float* q, float* wd, float* maxraw)
{
    if (C == 64) {
        size_t smk = (size_t)(NPTS * 65 * 2) * 4;
        cudaFuncSetAttribute(k_knn<64>, cudaFuncAttributeMaxDynamicSharedMemorySize, (int)smk);
        k_knn<64><<<BATCH, 64, smk>>>(xin);
    } else {
        size_t smk = (size_t)(NPTS * 129 + NPTS * 65) * 4;
        cudaFuncSetAttribute(k_knn<128>, cudaFuncAttributeMaxDynamicSharedMemorySize, (int)smk);
        k_knn<128><<<BATCH, 64, smk>>>(xin);
    }
    k_wdiff<<<(C * C1 + 255) / 256, 256>>>(w1, C, C1);
    k_gemm<<<dim3(C1 / 64, BNTOT / 64), 256>>>(xin, w1 + (size_t)C * C1, p, BNTOT, C, C1);
    k_gemm<<<dim3(C1 / 64, BNTOT / 64), 256>>>(xin, wd, q, BNTOT, C, C1);
    k_zero_stats<<<1, 512>>>();
    k_edgestats<<<BATCH, C1>>>(p, q, C1);
    k_finalize<<<1, 512>>>(g1, b1, C1, 1.f / (float)NEDGE);
    k_zero_stats<<<1, 512>>>();
    size_t sm2 = gemm2_smem(C1);
    dim3 grid2(BATCH, C2 / 64);
    if (C1 == 64) {
        cudaFuncSetAttribute(k_gemm2<64>, cudaFuncAttributeMaxDynamicSharedMemorySize, (int)sm2);
        k_gemm2<64><<<grid2, 256, sm2>>>(p, q, w2, C2, maxraw);
    } else if (C1 == 128) {
        cudaFuncSetAttribute(k_gemm2<128>, cudaFuncAttributeMaxDynamicSharedMemorySize, (int)sm2);
        k_gemm2<128><<<grid2, 256, sm2>>>(p, q, w2, C2, maxraw);
    } else {
        cudaFuncSetAttribute(k_gemm2<256>, cudaFuncAttributeMaxDynamicSharedMemorySize, (int)sm2);
        k_gemm2<256><<<grid2, 256, sm2>>>(p, q, w2, C2, maxraw);
    }
    k_finalize<<<1, 512>>>(g2, b2, C2, 1.f / (float)NEDGE);
    k_maxfix<<<(BNTOT * C2) / 256, 256>>>(maxraw, outh, BNTOT * C2, C2 - 1);
}

extern "C" void kernel_launch(void* const* d_in, const int* in_sizes, int n_in,
                              void* d_out, int out_size)
{
    const float* x    = (const float*)d_in[0];
    const float* w_in = (const float*)d_in[2];
    const float* g_in = (const float*)d_in[3];
    const float* b_in = (const float*)d_in[4];
    const float* w1a  = (const float*)d_in[5];
    const float* g1a  = (const float*)d_in[6];
    const float* b1a  = (const float*)d_in[7];
    const float* w1b  = (const float*)d_in[8];
    const float* g1b  = (const float*)d_in[9];
    const float* b1b  = (const float*)d_in[10];
    const float* w2a  = (const float*)d_in[11];
    const float* g2a  = (const float*)d_in[12];
    const float* b2a  = (const float*)d_in[13];
    const float* w2b  = (const float*)d_in[14];
    const float* g2b  = (const float*)d_in[15];
    const float* b2b  = (const float*)d_in[16];
    const float* w3a  = (const float*)d_in[17];
    const float* g3a  = (const float*)d_in[18];
    const float* b3a  = (const float*)d_in[19];
    const float* w3b  = (const float*)d_in[20];
    const float* g3b  = (const float*)d_in[21];
    const float* b3b  = (const float*)d_in[22];
    const float* wc1  = (const float*)d_in[23];
    const float* gc1  = (const float*)d_in[24];
    const float* bc1  = (const float*)d_in[25];
    const float* wc2  = (const float*)d_in[26];
    const float* gc2  = (const float*)d_in[27];
    const float* bc2  = (const float*)d_in[28];
    const float* wc3  = (const float*)d_in[29];
    const float* bc3  = (const float*)d_in[30];
    float* out = (float*)d_out;

    float *h0, *h1, *h2, *h3, *p, *q, *wd, *mr, *pooled, *z1, *z2;
    cudaGetSymbolAddress((void**)&h0, g_h0);
    cudaGetSymbolAddress((void**)&h1, g_h1);
    cudaGetSymbolAddress((void**)&h2, g_h2);
    cudaGetSymbolAddress((void**)&h3, g_h3);
    cudaGetSymbolAddress((void**)&p,  g_p);
    cudaGetSymbolAddress((void**)&q,  g_q);
    cudaGetSymbolAddress((void**)&wd, g_wd);
    cudaGetSymbolAddress((void**)&mr, g_maxraw);
    cudaGetSymbolAddress((void**)&pooled, g_pooled);
    cudaGetSymbolAddress((void**)&z1, g_z1);
    cudaGetSymbolAddress((void**)&z2, g_z2);

    // input MLP: h0 = lrelu(bn(x @ w_in))
    k_gemm<<<dim3(1, BNTOT / 64), 256>>>(x, w_in, h0, BNTOT, 6, 64);
    k_zero_stats<<<1, 512>>>();
    k_colstats<<<256, 64>>>(h0, BNTOT, 64, BNTOT / 256);
    k_finalize<<<1, 512>>>(g_in, b_in, 64, 1.f / (float)BNTOT);
    k_bnlrelu<<<(BNTOT * 64) / 256, 256>>>(h0, h0, BNTOT * 64, 63);

    // three EdgeConv blocks
    run_conv(h0, 64,  w1a, g1a, b1a, w1b, g1b, b1b, h1, 64, 64,  p, q, wd, mr);
    run_conv(h1, 64,  w2a, g2a, b2a, w2b, g2b, b2b, h2, 128, 128, p, q, wd, mr);
    run_conv(h2, 128, w3a, g3a, b3a, w3b, g3b, b3b, h3, 256, 256, p, q, wd, mr);

    // pooling + head
    k_pool<<<BATCH, 448>>>();

    k_gemm<<<dim3(8, BATCH / 64), 256>>>(pooled, wc1, z1, BATCH, 896, 512);
    k_zero_stats<<<1, 512>>>();
    k_colstats<<<8, 512>>>(z1, BATCH, 512, BATCH / 8);
    k_finalize<<<1, 512>>>(gc1, bc1, 512, 1.f / (float)BATCH);
    k_bnlrelu<<<(BATCH * 512) / 256, 256>>>(z1, z1, BATCH * 512, 511);

    k_gemm<<<dim3(4, BATCH / 64), 256>>>(z1, wc2, z2, BATCH, 512, 256);
    k_zero_stats<<<1, 512>>>();
    k_colstats<<<8, 256>>>(z2, BATCH, 256, BATCH / 8);
    k_finalize<<<1, 512>>>(gc2, bc2, 256, 1.f / (float)BATCH);
    k_bnlrelu<<<(BATCH * 256) / 256, 256>>>(z2, z2, BATCH * 256, 255);

    k_head_final<<<4, 256>>>(wc3, bc3, out);
}

// round 3
// speedup vs baseline: 1.0013x; 1.0013x over previous
#include <cuda_runtime.h>

#define BATCH 512
#define NPTS  64
#define KNBR  16
#define BNTOT 32768
#define NEDGE 524288
#define EPSV  1e-5f

__device__ float g_h0[BNTOT*64];
__device__ float g_h1[BNTOT*64];
__device__ float g_h2[BNTOT*128];
__device__ float g_h3[BNTOT*256];
__device__ float g_p [BNTOT*256];
__device__ float g_q [BNTOT*256];
__device__ float g_wd[256*256];
__device__ int   g_idx[NEDGE];
__device__ float g_maxraw[BNTOT*256];
__device__ float g_sum[512];
__device__ float g_sumsq[512];
__device__ float g_scale[512];
__device__ float g_shift[512];
__device__ float g_pooled[BATCH*896];
__device__ float g_z1[BATCH*512];
__device__ float g_z2[BATCH*256];

__device__ __forceinline__ void atomicMaxFloat(float* addr, float v) {
    if (v >= 0.f) atomicMax((int*)addr, __float_as_int(v));
    else          atomicMin((unsigned int*)addr, __float_as_uint(v));
}

// ---- generic fp32 GEMM: C[M,N] = A[M,K] @ W[K,N]; M%64==0, N%64==0 ----
__global__ __launch_bounds__(256) void k_gemm(
    const float* __restrict__ A, const float* __restrict__ W,
    float* __restrict__ Cc, int M, int Kd, int N)
{
    __shared__ float As[16][65];
    __shared__ float Ws[16][64];
    const int tid = threadIdx.x;
    const int row0 = blockIdx.y * 64, col0 = blockIdx.x * 64;
    const int ty = tid >> 4, tx = tid & 15;
    const int lkt = tid & 15, lrm = tid >> 4;
    const int wcn = tid & 63, wkt = tid >> 6;
    float acc[4][4];
#pragma unroll
    for (int r = 0; r < 4; r++)
#pragma unroll
        for (int c = 0; c < 4; c++) acc[r][c] = 0.f;

    for (int k0 = 0; k0 < Kd; k0 += 16) {
#pragma unroll
        for (int s = 0; s < 4; s++) {
            int kk = k0 + lkt;
            As[lkt][lrm + 16*s] = (kk < Kd) ? A[(size_t)(row0 + lrm + 16*s) * Kd + kk] : 0.f;
        }
#pragma unroll
        for (int s = 0; s < 4; s++) {
            int kk = k0 + wkt + 4*s;
            Ws[wkt + 4*s][wcn] = (kk < Kd) ? W[(size_t)kk * N + col0 + wcn] : 0.f;
        }
        __syncthreads();
#pragma unroll
        for (int kk = 0; kk < 16; kk++) {
            float a0 = As[kk][ty*4+0], a1 = As[kk][ty*4+1];
            float a2 = As[kk][ty*4+2], a3 = As[kk][ty*4+3];
            float4 bv = *(const float4*)&Ws[kk][tx*4];
#pragma unroll
            for (int r = 0; r < 4; r++) {
                float a = (r==0)?a0:(r==1)?a1:(r==2)?a2:a3;
                acc[r][0] = fmaf(a, bv.x, acc[r][0]);
                acc[r][1] = fmaf(a, bv.y, acc[r][1]);
                acc[r][2] = fmaf(a, bv.z, acc[r][2]);
                acc[r][3] = fmaf(a, bv.w, acc[r][3]);
            }
        }
        __syncthreads();
    }
#pragma unroll
    for (int r = 0; r < 4; r++)
#pragma unroll
        for (int c = 0; c < 4; c++)
            Cc[(size_t)(row0 + ty*4 + r) * N + col0 + tx*4 + c] = acc[r][c];
}

// ---- kNN: per-batch 64x64 distances, 16 nearest (excluding self) ----
template<int C>
__global__ void k_knn(const float* __restrict__ x)
{
    extern __shared__ float s[];
    float* xs = s;
    float* ds = s + NPTS * (C + 1);
    const int b = blockIdx.x;
    for (int i = threadIdx.x; i < NPTS * C; i += 64) {
        int n = i / C, c = i - n * C;
        xs[n * (C + 1) + c] = x[(size_t)(b * NPTS + n) * C + c];
    }
    __syncthreads();
    const int n = threadIdx.x;
    for (int m = 0; m < NPTS; m++) {
        float acc = 0.f;
#pragma unroll 8
        for (int c = 0; c < C; c++) {
            float d = xs[n * (C + 1) + c] - xs[m * (C + 1) + c];
            acc = fmaf(d, d, acc);
        }
        ds[n * 65 + m] = acc;
    }
    for (int sIt = 0; sIt < KNBR + 1; sIt++) {
        float best = 3.4e38f; int bi = 0;
        for (int m = 0; m < NPTS; m++) {
            float v = ds[n * 65 + m];
            if (v < best) { best = v; bi = m; }
        }
        ds[n * 65 + bi] = 3.4e38f;
        if (sIt > 0) g_idx[(b * NPTS + n) * KNBR + sIt - 1] = bi;
    }
}

__global__ void k_wdiff(const float* __restrict__ w1, int C, int C1)
{
    int i = blockIdx.x * blockDim.x + threadIdx.x;
    if (i < C * C1) g_wd[i] = w1[i] - w1[C * C1 + i];
}

__global__ void k_zero_stats()
{
    g_sum[threadIdx.x] = 0.f; g_sumsq[threadIdx.x] = 0.f;
}

__global__ void k_colstats(const float* __restrict__ X, int M, int Ncol, int rpb)
{
    int c = threadIdx.x;
    int r0 = blockIdx.x * rpb;
    int r1 = min(r0 + rpb, M);
    float s = 0.f, s2 = 0.f;
    for (int r = r0; r < r1; r++) {
        float v = X[(size_t)r * Ncol + c];
        s += v; s2 = fmaf(v, v, s2);
    }
    atomicAdd(&g_sum[c], s);
    atomicAdd(&g_sumsq[c], s2);
}

// bn1 stats over edges of t = p[n] + q[idx[n,k]]
__global__ void k_edgestats(const float* __restrict__ p, const float* __restrict__ q, int C1)
{
    const int b = blockIdx.x;
    const int c = threadIdx.x;
    __shared__ int idxs[NPTS * KNBR];
    for (int i = threadIdx.x; i < NPTS * KNBR; i += blockDim.x)
        idxs[i] = g_idx[b * NPTS * KNBR + i];
    __syncthreads();
    float s = 0.f, s2 = 0.f;
    for (int n = 0; n < NPTS; n++) {
        float pv = p[(size_t)(b * NPTS + n) * C1 + c];
#pragma unroll
        for (int k = 0; k < KNBR; k++) {
            int j = idxs[n * KNBR + k];
            float v = pv + q[(size_t)(b * NPTS + j) * C1 + c];
            s += v; s2 = fmaf(v, v, s2);
        }
    }
    atomicAdd(&g_sum[c], s);
    atomicAdd(&g_sumsq[c], s2);
}

__global__ void k_finalize(const float* __restrict__ g, const float* __restrict__ bb,
                           int C, float invcnt)
{
    int c = threadIdx.x;
    if (c < C) {
        float m  = g_sum[c] * invcnt;
        float vv = g_sumsq[c] * invcnt - m * m;
        float sc = g[c] * rsqrtf(vv + EPSV);
        g_scale[c] = sc;
        g_shift[c] = bb[c] - m * sc;
    }
}

__global__ void k_bnlrelu(const float* __restrict__ X, float* __restrict__ Y,
                          int total, int mask)
{
    int i = blockIdx.x * blockDim.x + threadIdx.x;
    if (i < total) {
        int c = i & mask;
        float v = fmaf(X[i], g_scale[c], g_shift[c]);
        Y[i] = fmaxf(v, 0.2f * v);
    }
}

__global__ void k_maxfix(const float* __restrict__ raw, float* __restrict__ Y,
                         int total, int mask)
{
    int i = blockIdx.x * blockDim.x + threadIdx.x;
    if (i < total) {
        float v = raw[i];
        if (v < -3.0e38f) Y[i] = 0.f;
        else {
            int c = i & mask;
            float t = fmaf(v, g_scale[c], g_shift[c]);
            Y[i] = fmaxf(t, 0.2f * t);
        }
    }
}

// ---- fused per-edge GEMM2 + bn2 stats + scatter-max ----
// grid (BATCH, C2/64), block 256. One block: all 1024 edges of batch b,
// 64 output channels [cb, cb+64).
template<int C1>
__global__ __launch_bounds__(256, 1) void k_gemm2(
    const float* __restrict__ p, const float* __restrict__ q,
    const float* __restrict__ w2, int C2, float* __restrict__ omg)
{
    extern __shared__ float sm[];
    constexpr int PS = C1 + 1;
    float* p_s  = sm;
    float* q_s  = p_s + NPTS * PS;
    float* w_s  = q_s + NPTS * PS;
    float* om   = w_s + C1 * 64;
    float* ssum = om + 64 * 65;
    float* ssq  = ssum + 64;
    int*   idxs = (int*)(ssq + 64);

    const int b = blockIdx.x, cb = blockIdx.y * 64;
    const int tid = threadIdx.x;

    for (int i = tid; i < NPTS * C1; i += 256) {
        int n = i / C1, c = i - n * C1;
        float sc = g_scale[c], sh = g_shift[c];
        p_s[n * PS + c] = fmaf(p[(size_t)(b * NPTS + n) * C1 + c], sc, sh);
        q_s[n * PS + c] = q[(size_t)(b * NPTS + n) * C1 + c] * sc;
    }
    for (int i = tid; i < C1 * 64; i += 256) {
        int k = i >> 6, c = i & 63;
        w_s[i] = w2[(size_t)k * C2 + cb + c];
    }
    for (int i = tid; i < NPTS * KNBR; i += 256) idxs[i] = g_idx[b * NPTS * KNBR + i];
    const float NEGINF = __int_as_float(0xff800000);
    for (int i = tid; i < 64 * 65; i += 256) om[i] = NEGINF;
    if (tid < 64) { ssum[tid] = 0.f; ssq[tid] = 0.f; }
    __syncthreads();

    const int cs = tid & 3;
    const int es = tid >> 2;
    const int cOff = cs * 16;
    float lsum[16], lsq[16];
#pragma unroll
    for (int c = 0; c < 16; c++) { lsum[c] = 0.f; lsq[c] = 0.f; }

#pragma unroll 1
    for (int pass = 0; pass < 4; pass++) {
        const int e0 = pass * 256 + es * 4;
        const int n = e0 >> 4;
        const int j0 = idxs[e0], j1 = idxs[e0+1], j2 = idxs[e0+2], j3 = idxs[e0+3];
        const float* pr = p_s + n * PS;
        const float* qa = q_s + j0 * PS;
        const float* qb = q_s + j1 * PS;
        const float* qc = q_s + j2 * PS;
        const float* qd = q_s + j3 * PS;
        float acc[4][16];
#pragma unroll
        for (int v = 0; v < 4; v++)
#pragma unroll
            for (int c = 0; c < 16; c++) acc[v][c] = 0.f;

#pragma unroll 4
        for (int i = 0; i < C1; i++) {
            float pv = pr[i];
            float h0 = pv + qa[i]; h0 = fmaxf(h0, 0.2f * h0);
            float h1 = pv + qb[i]; h1 = fmaxf(h1, 0.2f * h1);
            float h2 = pv + qc[i]; h2 = fmaxf(h2, 0.2f * h2);
            float h3 = pv + qd[i]; h3 = fmaxf(h3, 0.2f * h3);
            const float4* wr = (const float4*)(w_s + i * 64 + cOff);
            float4 w0 = wr[0], w1 = wr[1], w2v = wr[2], w3 = wr[3];
            float wv[16];
            *(float4*)&wv[0]  = w0; *(float4*)&wv[4]  = w1;
            *(float4*)&wv[8]  = w2v; *(float4*)&wv[12] = w3;
#pragma unroll
            for (int c = 0; c < 16; c++) {
                acc[0][c] = fmaf(h0, wv[c], acc[0][c]);
                acc[1][c] = fmaf(h1, wv[c], acc[1][c]);
                acc[2][c] = fmaf(h2, wv[c], acc[2][c]);
                acc[3][c] = fmaf(h3, wv[c], acc[3][c]);
            }
        }
#pragma unroll
        for (int v = 0; v < 4; v++) {
            int j = (v==0)?j0:(v==1)?j1:(v==2)?j2:j3;
            float* obase = om + j * 65 + cOff;
#pragma unroll
            for (int c = 0; c < 16; c++) {
                float y = acc[v][c];
                lsum[c] += y;
                lsq[c] = fmaf(y, y, lsq[c]);
                if (y > obase[c]) atomicMaxFloat(&obase[c], y);
            }
        }
    }
#pragma unroll
    for (int c = 0; c < 16; c++) {
        atomicAdd(&ssum[cOff + c], lsum[c]);
        atomicAdd(&ssq[cOff + c],  lsq[c]);
    }
    __syncthreads();
    if (tid < 64) {
        atomicAdd(&g_sum[cb + tid], ssum[tid]);
        atomicAdd(&g_sumsq[cb + tid], ssq[tid]);
    }
    for (int i = tid; i < NPTS * 64; i += 256) {
        int jj = i >> 6, c = i & 63;
        omg[(size_t)(b * NPTS + jj) * C2 + cb + c] = om[jj * 65 + c];
    }
}

__global__ void k_pool()
{
    const int b = blockIdx.x;
    const int c = threadIdx.x;   // 448
    const float* src; int cc, Cs;
    if (c < 64)       { src = g_h1; cc = c;       Cs = 64; }
    else if (c < 192) { src = g_h2; cc = c - 64;  Cs = 128; }
    else              { src = g_h3; cc = c - 192; Cs = 256; }
    float s = 0.f, mx = -3.4e38f;
    for (int n = 0; n < NPTS; n++) {
        float v = src[(size_t)(b * NPTS + n) * Cs + cc];
        s += v; mx = fmaxf(mx, v);
    }
    g_pooled[b * 896 + c]       = s * (1.f / 64.f);
    g_pooled[b * 896 + 448 + c] = mx;
}

__global__ void k_head_final(const float* __restrict__ wc3, const float* __restrict__ bc3,
                             float* __restrict__ out)
{
    int i = blockIdx.x * blockDim.x + threadIdx.x;
    if (i < BATCH * 2) {
        int bb = i >> 1, o = i & 1;
        float s = 0.f;
#pragma unroll 8
        for (int c = 0; c < 256; c++)
            s = fmaf(g_z2[bb * 256 + c], wc3[c * 2 + o], s);
        out[i] = s + bc3[o];
    }
}

// ---------------- host side ----------------
static size_t gemm2_smem(int C1) {
    return (size_t)(2 * NPTS * (C1 + 1) + C1 * 64 + 64 * 65 + 128 + NPTS * KNBR) * 4;
}

static void run_conv(const float* xin, int C,
                     const float* w1, const float* g1, const float* b1,
                     const float* w2, const float* g2, const float* b2,
                     float* outh, int C1, int C2,
                     float* p, float* q, float* wd, float* maxraw)
{
    if (C == 64) {
        size_t smk = (size_t)(NPTS * 65 * 2) * 4;
        cudaFuncSetAttribute(k_knn<64>, cudaFuncAttributeMaxDynamicSharedMemorySize, (int)smk);
        k_knn<64><<<BATCH, 64, smk>>>(xin);
    } else {
        size_t smk = (size_t)(NPTS * 129 + NPTS * 65) * 4;
        cudaFuncSetAttribute(k_knn<128>, cudaFuncAttributeMaxDynamicSharedMemorySize, (int)smk);
        k_knn<128><<<BATCH, 64, smk>>>(xin);
    }
    k_wdiff<<<(C * C1 + 255) / 256, 256>>>(w1, C, C1);
    k_gemm<<<dim3(C1 / 64, BNTOT / 64), 256>>>(xin, w1 + (size_t)C * C1, p, BNTOT, C, C1);
    k_gemm<<<dim3(C1 / 64, BNTOT / 64), 256>>>(xin, wd, q, BNTOT, C, C1);
    k_zero_stats<<<1, 512>>>();
    k_edgestats<<<BATCH, C1>>>(p, q, C1);
    k_finalize<<<1, 512>>>(g1, b1, C1, 1.f / (float)NEDGE);
    k_zero_stats<<<1, 512>>>();
    size_t sm2 = gemm2_smem(C1);
    dim3 grid2(BATCH, C2 / 64);
    if (C1 == 64) {
        cudaFuncSetAttribute(k_gemm2<64>, cudaFuncAttributeMaxDynamicSharedMemorySize, (int)sm2);
        k_gemm2<64><<<grid2, 256, sm2>>>(p, q, w2, C2, maxraw);
    } else if (C1 == 128) {
        cudaFuncSetAttribute(k_gemm2<128>, cudaFuncAttributeMaxDynamicSharedMemorySize, (int)sm2);
        k_gemm2<128><<<grid2, 256, sm2>>>(p, q, w2, C2, maxraw);
    } else {
        cudaFuncSetAttribute(k_gemm2<256>, cudaFuncAttributeMaxDynamicSharedMemorySize, (int)sm2);
        k_gemm2<256><<<grid2, 256, sm2>>>(p, q, w2, C2, maxraw);
    }
    k_finalize<<<1, 512>>>(g2, b2, C2, 1.f / (float)NEDGE);
    k_maxfix<<<(BNTOT * C2) / 256, 256>>>(maxraw, outh, BNTOT * C2, C2 - 1);
}

extern "C" void kernel_launch(void* const* d_in, const int* in_sizes, int n_in,
                              void* d_out, int out_size)
{
    const float* x    = (const float*)d_in[0];
    const float* w_in = (const float*)d_in[2];
    const float* g_in = (const float*)d_in[3];
    const float* b_in = (const float*)d_in[4];
    const float* w1a  = (const float*)d_in[5];
    const float* g1a  = (const float*)d_in[6];
    const float* b1a  = (const float*)d_in[7];
    const float* w1b  = (const float*)d_in[8];
    const float* g1b  = (const float*)d_in[9];
    const float* b1b  = (const float*)d_in[10];
    const float* w2a  = (const float*)d_in[11];
    const float* g2a  = (const float*)d_in[12];
    const float* b2a  = (const float*)d_in[13];
    const float* w2b  = (const float*)d_in[14];
    const float* g2b  = (const float*)d_in[15];
    const float* b2b  = (const float*)d_in[16];
    const float* w3a  = (const float*)d_in[17];
    const float* g3a  = (const float*)d_in[18];
    const float* b3a  = (const float*)d_in[19];
    const float* w3b  = (const float*)d_in[20];
    const float* g3b  = (const float*)d_in[21];
    const float* b3b  = (const float*)d_in[22];
    const float* wc1  = (const float*)d_in[23];
    const float* gc1  = (const float*)d_in[24];
    const float* bc1  = (const float*)d_in[25];
    const float* wc2  = (const float*)d_in[26];
    const float* gc2  = (const float*)d_in[27];
    const float* bc2  = (const float*)d_in[28];
    const float* wc3  = (const float*)d_in[29];
    const float* bc3  = (const float*)d_in[30];
    float* out = (float*)d_out;

    float *h0, *h1, *h2, *h3, *p, *q, *wd, *mr, *pooled, *z1, *z2;
    cudaGetSymbolAddress((void**)&h0, g_h0);
    cudaGetSymbolAddress((void**)&h1, g_h1);
    cudaGetSymbolAddress((void**)&h2, g_h2);
    cudaGetSymbolAddress((void**)&h3, g_h3);
    cudaGetSymbolAddress((void**)&p,  g_p);
    cudaGetSymbolAddress((void**)&q,  g_q);
    cudaGetSymbolAddress((void**)&wd, g_wd);
    cudaGetSymbolAddress((void**)&mr, g_maxraw);
    cudaGetSymbolAddress((void**)&pooled, g_pooled);
    cudaGetSymbolAddress((void**)&z1, g_z1);
    cudaGetSymbolAddress((void**)&z2, g_z2);

    // input MLP: h0 = lrelu(bn(x @ w_in))
    k_gemm<<<dim3(1, BNTOT / 64), 256>>>(x, w_in, h0, BNTOT, 6, 64);
    k_zero_stats<<<1, 512>>>();
    k_colstats<<<256, 64>>>(h0, BNTOT, 64, BNTOT / 256);
    k_finalize<<<1, 512>>>(g_in, b_in, 64, 1.f / (float)BNTOT);
    k_bnlrelu<<<(BNTOT * 64) / 256, 256>>>(h0, h0, BNTOT * 64, 63);

    // three EdgeConv blocks
    run_conv(h0, 64,  w1a, g1a, b1a, w1b, g1b, b1b, h1, 64, 64,  p, q, wd, mr);
    run_conv(h1, 64,  w2a, g2a, b2a, w2b, g2b, b2b, h2, 128, 128, p, q, wd, mr);
    run_conv(h2, 128, w3a, g3a, b3a, w3b, g3b, b3b, h3, 256, 256, p, q, wd, mr);

    // pooling + head
    k_pool<<<BATCH, 448>>>();

    k_gemm<<<dim3(8, BATCH / 64), 256>>>(pooled, wc1, z1, BATCH, 896, 512);
    k_zero_stats<<<1, 512>>>();
    k_colstats<<<8, 512>>>(z1, BATCH, 512, BATCH / 8);
    k_finalize<<<1, 512>>>(gc1, bc1, 512, 1.f / (float)BATCH);
    k_bnlrelu<<<(BATCH * 512) / 256, 256>>>(z1, z1, BATCH * 512, 511);

    k_gemm<<<dim3(4, BATCH / 64), 256>>>(z1, wc2, z2, BATCH, 512, 256);
    k_zero_stats<<<1, 512>>>();
    k_colstats<<<8, 256>>>(z2, BATCH, 256, BATCH / 8);
    k_finalize<<<1, 512>>>(gc2, bc2, 256, 1.f / (float)BATCH);
    k_bnlrelu<<<(BATCH * 256) / 256, 256>>>(z2, z2, BATCH * 256, 255);

    k_head_final<<<4, 256>>>(wc3, bc3, out);
}

// round 5
// speedup vs baseline: 1.3993x; 1.3974x over previous
#include <cuda_runtime.h>
#include <stdint.h>

#define BATCH 512
#define NPTS  64
#define KNBR  16
#define BNTOT 32768
#define NEDGE 524288
#define EPSV  1e-5f

__device__ float g_h0[BNTOT*64];
__device__ float g_h1[BNTOT*64];
__device__ float g_h2[BNTOT*128];
__device__ float g_h3[BNTOT*256];
__device__ float g_p [BNTOT*256];
__device__ float g_q [BNTOT*256];
__device__ float g_wd[256*256];
__device__ int   g_idx[NEDGE];
__device__ float g_maxraw[BNTOT*256];
__device__ float g_sum[512];
__device__ float g_sumsq[512];
__device__ float g_scale[512];
__device__ float g_shift[512];
__device__ float g_pooled[BATCH*896];
__device__ float g_z1[BATCH*512];
__device__ float g_z2[BATCH*256];

__device__ __forceinline__ void atomicMaxFloat(float* a, float v) {
    if (v >= 0.f) atomicMax((int*)a, __float_as_int(v));
    else          atomicMin((unsigned*)a, __float_as_uint(v));
}
__device__ __forceinline__ unsigned sm_u32(const void* p) {
    return (unsigned)__cvta_generic_to_shared(p);
}
__device__ __forceinline__ unsigned bfpack(float lo, float hi) {
    unsigned r;
    asm("cvt.rn.bf16x2.f32 %0, %1, %2;" : "=r"(r) : "f"(hi), "f"(lo));
    return r;
}
#define SW128X(o) ((o) ^ (((o)>>3)&0x70))
__device__ __forceinline__ void ldmx4(unsigned r[4], unsigned a) {
    asm volatile("ldmatrix.sync.aligned.m8n8.x4.shared.b16 {%0,%1,%2,%3},[%4];"
        : "=r"(r[0]), "=r"(r[1]), "=r"(r[2]), "=r"(r[3]) : "r"(a));
}
__device__ __forceinline__ void mmabf(float d[4], const unsigned a[4], const unsigned b[2]) {
    asm volatile("mma.sync.aligned.m16n8k16.row.col.f32.bf16.bf16.f32 "
        "{%0,%1,%2,%3},{%4,%5,%6,%7},{%8,%9},{%0,%1,%2,%3};"
        : "+f"(d[0]), "+f"(d[1]), "+f"(d[2]), "+f"(d[3])
        : "r"(a[0]), "r"(a[1]), "r"(a[2]), "r"(a[3]), "r"(b[0]), "r"(b[1]));
}

// ---- fp32 GEMM for p/q + head ----
__global__ __launch_bounds__(256) void k_gemm(
    const float* __restrict__ A, const float* __restrict__ W,
    float* __restrict__ Cc, int M, int Kd, int N)
{
    __shared__ float As[16][65];
    __shared__ float Ws[16][64];
    const int tid = threadIdx.x;
    const int row0 = blockIdx.y * 64, col0 = blockIdx.x * 64;
    const int ty = tid >> 4, tx = tid & 15;
    const int lkt = tid & 15, lrm = tid >> 4;
    const int wcn = tid & 63, wkt = tid >> 6;
    float acc[4][4];
#pragma unroll
    for (int r = 0; r < 4; r++)
#pragma unroll
        for (int c = 0; c < 4; c++) acc[r][c] = 0.f;
    for (int k0 = 0; k0 < Kd; k0 += 16) {
#pragma unroll
        for (int s = 0; s < 4; s++) {
            int kk = k0 + lkt;
            As[lkt][lrm + 16*s] = (kk < Kd) ? A[(size_t)(row0 + lrm + 16*s) * Kd + kk] : 0.f;
        }
#pragma unroll
        for (int s = 0; s < 4; s++) {
            int kk = k0 + wkt + 4*s;
            Ws[wkt + 4*s][wcn] = (kk < Kd) ? W[(size_t)kk * N + col0 + wcn] : 0.f;
        }
        __syncthreads();
#pragma unroll
        for (int kk = 0; kk < 16; kk++) {
            float a0 = As[kk][ty*4+0], a1 = As[kk][ty*4+1];
            float a2 = As[kk][ty*4+2], a3 = As[kk][ty*4+3];
            float4 bv = *(const float4*)&Ws[kk][tx*4];
#pragma unroll
            for (int r = 0; r < 4; r++) {
                float a = (r==0)?a0:(r==1)?a1:(r==2)?a2:a3;
                acc[r][0] = fmaf(a, bv.x, acc[r][0]);
                acc[r][1] = fmaf(a, bv.y, acc[r][1]);
                acc[r][2] = fmaf(a, bv.z, acc[r][2]);
                acc[r][3] = fmaf(a, bv.w, acc[r][3]);
            }
        }
        __syncthreads();
    }
#pragma unroll
    for (int r = 0; r < 4; r++)
#pragma unroll
        for (int c = 0; c < 4; c++)
            Cc[(size_t)(row0 + ty*4 + r) * N + col0 + tx*4 + c] = acc[r][c];
}

template<int C>
__global__ void k_knn(const float* __restrict__ x)
{
    extern __shared__ float s[];
    float* xs = s;
    float* ds = s + NPTS * (C + 1);
    const int b = blockIdx.x;
    for (int i = threadIdx.x; i < NPTS * C; i += 64) {
        int n = i / C, c = i - n * C;
        xs[n * (C + 1) + c] = x[(size_t)(b * NPTS + n) * C + c];
    }
    __syncthreads();
    const int n = threadIdx.x;
    for (int m = 0; m < NPTS; m++) {
        float acc = 0.f;
#pragma unroll 8
        for (int c = 0; c < C; c++) {
            float d = xs[n * (C + 1) + c] - xs[m * (C + 1) + c];
            acc = fmaf(d, d, acc);
        }
        ds[n * 65 + m] = acc;
    }
    for (int sIt = 0; sIt < KNBR + 1; sIt++) {
        float best = 3.4e38f; int bi = 0;
        for (int m = 0; m < NPTS; m++) {
            float v = ds[n * 65 + m];
            if (v < best) { best = v; bi = m; }
        }
        ds[n * 65 + bi] = 3.4e38f;
        if (sIt > 0) g_idx[(b * NPTS + n) * KNBR + sIt - 1] = bi;
    }
}

__global__ void k_wdiff(const float* __restrict__ w1, int C, int C1)
{
    int i = blockIdx.x * blockDim.x + threadIdx.x;
    if (i < C * C1) g_wd[i] = w1[i] - w1[C * C1 + i];
}
__global__ void k_zero_stats()
{
    g_sum[threadIdx.x] = 0.f; g_sumsq[threadIdx.x] = 0.f;
}
__global__ void k_colstats(const float* __restrict__ X, int M, int Ncol, int rpb)
{
    int c = threadIdx.x;
    int r0 = blockIdx.x * rpb, r1 = min(r0 + rpb, M);
    float s = 0.f, s2 = 0.f;
    for (int r = r0; r < r1; r++) {
        float v = X[(size_t)r * Ncol + c];
        s += v; s2 = fmaf(v, v, s2);
    }
    atomicAdd(&g_sum[c], s);
    atomicAdd(&g_sumsq[c], s2);
}
__global__ void k_edgestats(const float* __restrict__ p, const float* __restrict__ q, int C1)
{
    const int b = blockIdx.x;
    const int c = threadIdx.x;
    __shared__ int idxs[NPTS * KNBR];
    for (int i = threadIdx.x; i < NPTS * KNBR; i += blockDim.x)
        idxs[i] = g_idx[b * NPTS * KNBR + i];
    __syncthreads();
    float s = 0.f, s2 = 0.f;
    for (int n = 0; n < NPTS; n++) {
        float pv = p[(size_t)(b * NPTS + n) * C1 + c];
#pragma unroll
        for (int k = 0; k < KNBR; k++) {
            int j = idxs[n * KNBR + k];
            float v = pv + q[(size_t)(b * NPTS + j) * C1 + c];
            s += v; s2 = fmaf(v, v, s2);
        }
    }
    atomicAdd(&g_sum[c], s);
    atomicAdd(&g_sumsq[c], s2);
}
__global__ void k_finalize(const float* __restrict__ g, const float* __restrict__ bb,
                           int C, float invcnt)
{
    int c = threadIdx.x;
    if (c < C) {
        float m  = g_sum[c] * invcnt;
        float vv = g_sumsq[c] * invcnt - m * m;
        float sc = g[c] * rsqrtf(vv + EPSV);
        g_scale[c] = sc;
        g_shift[c] = bb[c] - m * sc;
    }
}
__global__ void k_bnlrelu(const float* __restrict__ X, float* __restrict__ Y,
                          int total, int mask)
{
    int i = blockIdx.x * blockDim.x + threadIdx.x;
    if (i < total) {
        int c = i & mask;
        float v = fmaf(X[i], g_scale[c], g_shift[c]);
        Y[i] = fmaxf(v, 0.2f * v);
    }
}
__global__ void k_maxfix(const float* __restrict__ raw, float* __restrict__ Y,
                         int total, int mask)
{
    int i = blockIdx.x * blockDim.x + threadIdx.x;
    if (i < total) {
        float v = raw[i];
        if (v < -3.0e38f) Y[i] = 0.f;
        else {
            int c = i & mask;
            float t = fmaf(v, g_scale[c], g_shift[c]);
            Y[i] = fmaxf(t, 0.2f * t);
        }
    }
}

// ---- HMMA edge GEMM2 + bn2 stats + scatter-max ----
template<int C1> struct Lay {
    static constexpr int IDX = 0;
    static constexpr int PT  = 4096;
    static constexpr int QT  = PT + C1*36;
    static constexpr int BHI = QT + C1*264;
    static constexpr int BLO = BHI + (C1/64)*8192;
    static constexpr int AHI = BLO + (C1/64)*8192;
    static constexpr int ALO = AHI + 16384;
    static constexpr int OM  = ALO + 16384;
    static constexpr int TOT = OM + 64*65*4;
};

template<int C1>
__global__ __launch_bounds__(128, 1) void k_hmma2(
    const float* __restrict__ p, const float* __restrict__ q,
    const float* __restrict__ w2, int C2, float* __restrict__ omg)
{
    using L = Lay<C1>;
    constexpr int KC = C1 / 64;
    extern __shared__ char sm[];
    const unsigned smb = sm_u32(sm);
    int*   idxs = (int*)(sm + L::IDX);
    float* p_t  = (float*)(sm + L::PT);
    float* q_t  = (float*)(sm + L::QT);
    float* om   = (float*)(sm + L::OM);
    const int b = blockIdx.x, cb = blockIdx.y * 64;
    const int tid = threadIdx.x, wid = tid >> 5, lane = tid & 31;

    for (int i = tid; i < 1024; i += 128) idxs[i] = g_idx[b * 1024 + i];
    for (int i = tid; i < 64 * C1; i += 128) {
        int j = i / C1, k = i - j * C1;
        q_t[k * 66 + j] = g_scale[k] * q[(size_t)(b * 64 + j) * C1 + k];
    }
    for (int i = tid; i < 64 * (C1 / 2); i += 128) {
        int n = i & 63, k0 = (i >> 6) * 2;
        float v0 = w2[(size_t)k0 * C2 + cb + n];
        float v1 = w2[(size_t)(k0 + 1) * C2 + cb + n];
        unsigned hp = bfpack(v0, v1);
        float l0 = v0 - __int_as_float(hp << 16);
        float l1 = v1 - __int_as_float(hp & 0xffff0000u);
        unsigned lp = bfpack(l0, l1);
        int sw = SW128X(n * 128 + (k0 & 63) * 2), tb = (k0 >> 6) * 8192;
        *(unsigned*)(sm + L::BHI + tb + sw) = hp;
        *(unsigned*)(sm + L::BLO + tb + sw) = lp;
    }
    const float NEGINF = __int_as_float(0xff800000);
    for (int i = tid; i < 64 * 65; i += 128) om[i] = NEGINF;

    float ls[16], lq[16];
#pragma unroll
    for (int s = 0; s < 16; s++) { ls[s] = 0.f; lq[s] = 0.f; }

    const int arow = wid * 32 + (lane & 15);
    const int acol = ((lane >> 4) & 1) * 8;
    const int brow = (lane & 7) + ((lane >> 4) & 1) * 8;
    const int bcol = ((lane >> 3) & 1) * 8;
    __syncthreads();

    for (int chunk = 0; chunk < 8; chunk++) {
        for (int i = tid; i < 8 * C1; i += 128) {
            int n = i / C1, k = i - n * C1;
            p_t[k * 9 + n] = fmaf(p[(size_t)(b * 64 + chunk * 8 + n) * C1 + k],
                                  g_scale[k], g_shift[k]);
        }
        float acc[2][8][4];
#pragma unroll
        for (int t = 0; t < 2; t++)
#pragma unroll
            for (int nt = 0; nt < 8; nt++)
#pragma unroll
                for (int r = 0; r < 4; r++) acc[t][nt][r] = 0.f;

        for (int kc = 0; kc < KC; kc++) {
            __syncthreads();
            {
                const int n8 = (tid >> 4) & 7;
                const int j = idxs[chunk * 128 + tid];
                char* ah = sm + L::AHI;
                char* al = sm + L::ALO;
#pragma unroll
                for (int kp = 0; kp < 32; kp++) {
                    int k = kc * 64 + kp * 2;
                    float f0 = p_t[k * 9 + n8]       + q_t[k * 66 + j];
                    float f1 = p_t[(k + 1) * 9 + n8] + q_t[(k + 1) * 66 + j];
                    f0 = fmaxf(f0, 0.2f * f0);
                    f1 = fmaxf(f1, 0.2f * f1);
                    unsigned hp = bfpack(f0, f1);
                    float l0 = f0 - __int_as_float(hp << 16);
                    float l1 = f1 - __int_as_float(hp & 0xffff0000u);
                    unsigned lp = bfpack(l0, l1);
                    int sw = SW128X(tid * 128 + kp * 4);
                    *(unsigned*)(ah + sw) = hp;
                    *(unsigned*)(al + sw) = lp;
                }
            }
            __syncthreads();
#pragma unroll
            for (int ks = 0; ks < 4; ks++) {
                unsigned ah[2][4], al[2][4], bh[4][4], bl[4][4];
#pragma unroll
                for (int t = 0; t < 2; t++) {
                    unsigned ra = smb + L::AHI +
                        SW128X((arow + t * 16) * 128 + (ks * 16 + acol) * 2);
                    ldmx4(ah[t], ra);
                    ldmx4(al[t], ra + 16384);
                }
#pragma unroll
                for (int g = 0; g < 4; g++) {
                    unsigned rb = smb + L::BHI + kc * 8192 +
                        SW128X((g * 16 + brow) * 128 + (ks * 16 + bcol) * 2);
                    ldmx4(bh[g], rb);
                    ldmx4(bl[g], rb + KC * 8192);
                }
#pragma unroll
                for (int t = 0; t < 2; t++)
#pragma unroll
                    for (int nt = 0; nt < 8; nt++) {
                        const unsigned* bhp = &bh[nt >> 1][(nt & 1) * 2];
                        const unsigned* blp = &bl[nt >> 1][(nt & 1) * 2];
                        mmabf(acc[t][nt], ah[t], bhp);
                        mmabf(acc[t][nt], ah[t], blp);
                        mmabf(acc[t][nt], al[t], bhp);
                    }
            }
        }
        // epilogue: stats + scatter-max
#pragma unroll
        for (int t = 0; t < 2; t++) {
            int e0 = chunk * 128 + wid * 32 + t * 16 + (lane >> 2);
            int ja = idxs[e0], jb = idxs[e0 + 8];
#pragma unroll
            for (int nt = 0; nt < 8; nt++) {
                int c0 = nt * 8 + (lane & 3) * 2;
                float y0 = acc[t][nt][0], y1 = acc[t][nt][1];
                float y2 = acc[t][nt][2], y3 = acc[t][nt][3];
                ls[nt*2]   += y0 + y2;
                lq[nt*2]    = fmaf(y0, y0, fmaf(y2, y2, lq[nt*2]));
                ls[nt*2+1] += y1 + y3;
                lq[nt*2+1]  = fmaf(y1, y1, fmaf(y3, y3, lq[nt*2+1]));
                float* oa = om + ja * 65 + c0;
                float* ob = om + jb * 65 + c0;
                if (y0 > oa[0]) atomicMaxFloat(oa,     y0);
                if (y1 > oa[1]) atomicMaxFloat(oa + 1, y1);
                if (y2 > ob[0]) atomicMaxFloat(ob,     y2);
                if (y3 > ob[1]) atomicMaxFloat(ob + 1, y3);
            }
        }
    }
#pragma unroll
    for (int s = 0; s < 16; s++) {
#pragma unroll
        for (int o = 4; o < 32; o <<= 1) {
            ls[s] += __shfl_xor_sync(~0u, ls[s], o);
            lq[s] += __shfl_xor_sync(~0u, lq[s], o);
        }
    }
    if (lane < 4) {
#pragma unroll
        for (int s = 0; s < 16; s++) {
            int c = (s >> 1) * 8 + lane * 2 + (s & 1);
            atomicAdd(&g_sum[cb + c], ls[s]);
            atomicAdd(&g_sumsq[cb + c], lq[s]);
        }
    }
    __syncthreads();
    for (int i = tid; i < 64 * 64; i += 128) {
        int jj = i >> 6, c = i & 63;
        omg[(size_t)(b * 64 + jj) * C2 + cb + c] = om[jj * 65 + c];
    }
}

__global__ void k_pool()
{
    const int b = blockIdx.x;
    const int c = threadIdx.x;
    const float* src; int cc, Cs;
    if (c < 64)       { src = g_h1; cc = c;       Cs = 64; }
    else if (c < 192) { src = g_h2; cc = c - 64;  Cs = 128; }
    else              { src = g_h3; cc = c - 192; Cs = 256; }
    float s = 0.f, mx = -3.4e38f;
    for (int n = 0; n < NPTS; n++) {
        float v = src[(size_t)(b * NPTS + n) * Cs + cc];
        s += v; mx = fmaxf(mx, v);
    }
    g_pooled[b * 896 + c]       = s * (1.f / 64.f);
    g_pooled[b * 896 + 448 + c] = mx;
}

__global__ void k_head_final(const float* __restrict__ wc3, const float* __restrict__ bc3,
                             float* __restrict__ out)
{
    int i = blockIdx.x * blockDim.x + threadIdx.x;
    if (i < BATCH * 2) {
        int bb = i >> 1, o = i & 1;
        float s = 0.f;
#pragma unroll 8
        for (int c = 0; c < 256; c++)
            s = fmaf(g_z2[bb * 256 + c], wc3[c * 2 + o], s);
        out[i] = s + bc3[o];
    }
}

// ---------------- host side ----------------
static void run_conv(const float* xin, int C,
                     const float* w1, const float* g1, const float* b1,
                     const float* w2, const float* g2, const float* b2,
                     float* outh, int C1, int C2,
                     float* p, float* q, float* wd, float* maxraw)
{
    if (C == 64) {
        size_t smk = (size_t)(NPTS * 65 * 2) * 4;
        cudaFuncSetAttribute(k_knn<64>, cudaFuncAttributeMaxDynamicSharedMemorySize, (int)smk);
        k_knn<64><<<BATCH, 64, smk>>>(xin);
    } else {
        size_t smk = (size_t)(NPTS * 129 + NPTS * 65) * 4;
        cudaFuncSetAttribute(k_knn<128>, cudaFuncAttributeMaxDynamicSharedMemorySize, (int)smk);
        k_knn<128><<<BATCH, 64, smk>>>(xin);
    }
    k_wdiff<<<(C * C1 + 255) / 256, 256>>>(w1, C, C1);
    k_gemm<<<dim3(C1 / 64, BNTOT / 64), 256>>>(xin, w1 + (size_t)C * C1, p, BNTOT, C, C1);
    k_gemm<<<dim3(C1 / 64, BNTOT / 64), 256>>>(xin, wd, q, BNTOT, C, C1);
    k_zero_stats<<<1, 512>>>();
    k_edgestats<<<BATCH, C1>>>(p, q, C1);
    k_finalize<<<1, 512>>>(g1, b1, C1, 1.f / (float)NEDGE);
    k_zero_stats<<<1, 512>>>();
    dim3 grid2(BATCH, C2 / 64);
    if (C1 == 64) {
        cudaFuncSetAttribute(k_hmma2<64>, cudaFuncAttributeMaxDynamicSharedMemorySize, Lay<64>::TOT);
        k_hmma2<64><<<grid2, 128, Lay<64>::TOT>>>(p, q, w2, C2, maxraw);
    } else if (C1 == 128) {
        cudaFuncSetAttribute(k_hmma2<128>, cudaFuncAttributeMaxDynamicSharedMemorySize, Lay<128>::TOT);
        k_hmma2<128><<<grid2, 128, Lay<128>::TOT>>>(p, q, w2, C2, maxraw);
    } else {
        cudaFuncSetAttribute(k_hmma2<256>, cudaFuncAttributeMaxDynamicSharedMemorySize, Lay<256>::TOT);
        k_hmma2<256><<<grid2, 128, Lay<256>::TOT>>>(p, q, w2, C2, maxraw);
    }
    k_finalize<<<1, 512>>>(g2, b2, C2, 1.f / (float)NEDGE);
    k_maxfix<<<(BNTOT * C2) / 256, 256>>>(maxraw, outh, BNTOT * C2, C2 - 1);
}

extern "C" void kernel_launch(void* const* d_in, const int* in_sizes, int n_in,
                              void* d_out, int out_size)
{
    const float* x    = (const float*)d_in[0];
    const float* w_in = (const float*)d_in[2];
    const float* g_in = (const float*)d_in[3];
    const float* b_in = (const float*)d_in[4];
    const float* w1a  = (const float*)d_in[5];
    const float* g1a  = (const float*)d_in[6];
    const float* b1a  = (const float*)d_in[7];
    const float* w1b  = (const float*)d_in[8];
    const float* g1b  = (const float*)d_in[9];
    const float* b1b  = (const float*)d_in[10];
    const float* w2a  = (const float*)d_in[11];
    const float* g2a  = (const float*)d_in[12];
    const float* b2a  = (const float*)d_in[13];
    const float* w2b  = (const float*)d_in[14];
    const float* g2b  = (const float*)d_in[15];
    const float* b2b  = (const float*)d_in[16];
    const float* w3a  = (const float*)d_in[17];
    const float* g3a  = (const float*)d_in[18];
    const float* b3a  = (const float*)d_in[19];
    const float* w3b  = (const float*)d_in[20];
    const float* g3b  = (const float*)d_in[21];
    const float* b3b  = (const float*)d_in[22];
    const float* wc1  = (const float*)d_in[23];
    const float* gc1  = (const float*)d_in[24];
    const float* bc1  = (const float*)d_in[25];
    const float* wc2  = (const float*)d_in[26];
    const float* gc2  = (const float*)d_in[27];
    const float* bc2  = (const float*)d_in[28];
    const float* wc3  = (const float*)d_in[29];
    const float* bc3  = (const float*)d_in[30];
    float* out = (float*)d_out;

    float *h0, *h1, *h2, *h3, *p, *q, *wd, *mr, *pooled, *z1, *z2;
    cudaGetSymbolAddress((void**)&h0, g_h0);
    cudaGetSymbolAddress((void**)&h1, g_h1);
    cudaGetSymbolAddress((void**)&h2, g_h2);
    cudaGetSymbolAddress((void**)&h3, g_h3);
    cudaGetSymbolAddress((void**)&p,  g_p);
    cudaGetSymbolAddress((void**)&q,  g_q);
    cudaGetSymbolAddress((void**)&wd, g_wd);
    cudaGetSymbolAddress((void**)&mr, g_maxraw);
    cudaGetSymbolAddress((void**)&pooled, g_pooled);
    cudaGetSymbolAddress((void**)&z1, g_z1);
    cudaGetSymbolAddress((void**)&z2, g_z2);

    k_gemm<<<dim3(1, BNTOT / 64), 256>>>(x, w_in, h0, BNTOT, 6, 64);
    k_zero_stats<<<1, 512>>>();
    k_colstats<<<256, 64>>>(h0, BNTOT, 64, BNTOT / 256);
    k_finalize<<<1, 512>>>(g_in, b_in, 64, 1.f / (float)BNTOT);
    k_bnlrelu<<<(BNTOT * 64) / 256, 256>>>(h0, h0, BNTOT * 64, 63);

    run_conv(h0, 64,  w1a, g1a, b1a, w1b, g1b, b1b, h1, 64, 64,  p, q, wd, mr);
    run_conv(h1, 64,  w2a, g2a, b2a, w2b, g2b, b2b, h2, 128, 128, p, q, wd, mr);
    run_conv(h2, 128, w3a, g3a, b3a, w3b, g3b, b3b, h3, 256, 256, p, q, wd, mr);

    k_pool<<<BATCH, 448>>>();

    k_gemm<<<dim3(8, BATCH / 64), 256>>>(pooled, wc1, z1, BATCH, 896, 512);
    k_zero_stats<<<1, 512>>>();
    k_colstats<<<8, 512>>>(z1, BATCH, 512, BATCH / 8);
    k_finalize<<<1, 512>>>(gc1, bc1, 512, 1.f / (float)BATCH);
    k_bnlrelu<<<(BATCH * 512) / 256, 256>>>(z1, z1, BATCH * 512, 511);

    k_gemm<<<dim3(4, BATCH / 64), 256>>>(z1, wc2, z2, BATCH, 512, 256);
    k_zero_stats<<<1, 512>>>();
    k_colstats<<<8, 256>>>(z2, BATCH, 256, BATCH / 8);
    k_finalize<<<1, 512>>>(gc2, bc2, 256, 1.f / (float)BATCH);
    k_bnlrelu<<<(BATCH * 256) / 256, 256>>>(z2, z2, BATCH * 256, 255);

    k_head_final<<<4, 256>>>(wc3, bc3, out);
}

// round 7
// speedup vs baseline: 1.5616x; 1.1160x over previous
#include <cuda_runtime.h>
#include <stdint.h>

#define BATCH 512
#define NPTS  64
#define KNBR  16
#define BNTOT 32768
#define NEDGE 524288
#define EPSV  1e-5f

__device__ float g_h0[BNTOT*64];
__device__ float g_h1[BNTOT*64];
__device__ float g_h2[BNTOT*128];
__device__ float g_h3[BNTOT*256];
__device__ float g_p [BNTOT*256];
__device__ float g_q [BNTOT*256];
__device__ float g_wd[256*256];
__device__ int   g_idx[NEDGE];
__device__ float g_maxraw[BNTOT*256];
__device__ float g_sum[512];
__device__ float g_sumsq[512];
__device__ float g_scale[512];
__device__ float g_shift[512];
__device__ float g_pooled[BATCH*896];
__device__ float g_z1[BATCH*512];
__device__ float g_z2[BATCH*256];

__device__ __forceinline__ void atomicMaxFloat(float* a, float v) {
    if (v >= 0.f) atomicMax((int*)a, __float_as_int(v));
    else          atomicMin((unsigned*)a, __float_as_uint(v));
}
__device__ __forceinline__ unsigned sm_u32(const void* p) {
    return (unsigned)__cvta_generic_to_shared(p);
}
__device__ __forceinline__ unsigned bfpack(float lo, float hi) {
    unsigned r;
    asm("cvt.rn.bf16x2.f32 %0, %1, %2;" : "=r"(r) : "f"(hi), "f"(lo));
    return r;
}
#define SW128X(o) ((o) ^ (((o)>>3)&0x70))
__device__ __forceinline__ void ldmx4(unsigned r[4], unsigned a) {
    asm volatile("ldmatrix.sync.aligned.m8n8.x4.shared.b16 {%0,%1,%2,%3},[%4];"
        : "=r"(r[0]), "=r"(r[1]), "=r"(r[2]), "=r"(r[3]) : "r"(a));
}
__device__ __forceinline__ void mmabf(float d[4], const unsigned a[4], const unsigned b[2]) {
    asm volatile("mma.sync.aligned.m16n8k16.row.col.f32.bf16.bf16.f32 "
        "{%0,%1,%2,%3},{%4,%5,%6,%7},{%8,%9},{%0,%1,%2,%3};"
        : "+f"(d[0]), "+f"(d[1]), "+f"(d[2]), "+f"(d[3])
        : "r"(a[0]), "r"(a[1]), "r"(a[2]), "r"(a[3]), "r"(b[0]), "r"(b[1]));
}

// ---- fp32 GEMM (h0, head, conv1/2 p/q) ----
__global__ __launch_bounds__(256) void k_gemm(
    const float* __restrict__ A, const float* __restrict__ W,
    float* __restrict__ Cc, int M, int Kd, int N)
{
    __shared__ float As[16][65];
    __shared__ float Ws[16][64];
    const int tid = threadIdx.x;
    const int row0 = blockIdx.y * 64, col0 = blockIdx.x * 64;
    const int ty = tid >> 4, tx = tid & 15;
    const int lkt = tid & 15, lrm = tid >> 4;
    const int wcn = tid & 63, wkt = tid >> 6;
    float acc[4][4];
#pragma unroll
    for (int r = 0; r < 4; r++)
#pragma unroll
        for (int c = 0; c < 4; c++) acc[r][c] = 0.f;
    for (int k0 = 0; k0 < Kd; k0 += 16) {
#pragma unroll
        for (int s = 0; s < 4; s++) {
            int kk = k0 + lkt;
            As[lkt][lrm + 16*s] = (kk < Kd) ? A[(size_t)(row0 + lrm + 16*s) * Kd + kk] : 0.f;
        }
#pragma unroll
        for (int s = 0; s < 4; s++) {
            int kk = k0 + wkt + 4*s;
            Ws[wkt + 4*s][wcn] = (kk < Kd) ? W[(size_t)kk * N + col0 + wcn] : 0.f;
        }
        __syncthreads();
#pragma unroll
        for (int kk = 0; kk < 16; kk++) {
            float a0 = As[kk][ty*4+0], a1 = As[kk][ty*4+1];
            float a2 = As[kk][ty*4+2], a3 = As[kk][ty*4+3];
            float4 bv = *(const float4*)&Ws[kk][tx*4];
#pragma unroll
            for (int r = 0; r < 4; r++) {
                float a = (r==0)?a0:(r==1)?a1:(r==2)?a2:a3;
                acc[r][0] = fmaf(a, bv.x, acc[r][0]);
                acc[r][1] = fmaf(a, bv.y, acc[r][1]);
                acc[r][2] = fmaf(a, bv.z, acc[r][2]);
                acc[r][3] = fmaf(a, bv.w, acc[r][3]);
            }
        }
        __syncthreads();
    }
#pragma unroll
    for (int r = 0; r < 4; r++)
#pragma unroll
        for (int c = 0; c < 4; c++)
            Cc[(size_t)(row0 + ty*4 + r) * N + col0 + tx*4 + c] = acc[r][c];
}

// ---- HMMA bf16-split GEMM (conv3 p/q only): K%64==0, M%128==0, N%64==0 ----
__global__ __launch_bounds__(256, 2) void k_hgemm(
    const float* __restrict__ A, const float* __restrict__ W,
    float* __restrict__ Cc, int M, int Kd, int N)
{
    __shared__ char sb[49152];   // AHI 0, ALO 16384, BHI 32768, BLO 40960
    const unsigned smb = sm_u32(sb);
    const int tid = threadIdx.x, wid = tid >> 5, lane = tid & 31;
    const int row0 = blockIdx.y * 128, col0 = blockIdx.x * 64;
    float acc[8][4];
#pragma unroll
    for (int nt = 0; nt < 8; nt++)
#pragma unroll
        for (int r = 0; r < 4; r++) acc[nt][r] = 0.f;
    const int arow = wid * 16 + (lane & 15);
    const int acol = ((lane >> 4) & 1) * 8;
    const int brow = (lane & 7) + ((lane >> 4) & 1) * 8;
    const int bcol = ((lane >> 3) & 1) * 8;

    for (int k0 = 0; k0 < Kd; k0 += 64) {
        __syncthreads();
        {
            int r = tid >> 1;
            const float* ar = A + (size_t)(row0 + r) * Kd + k0 + (tid & 1) * 32;
            int base = r * 128 + (tid & 1) * 64;
#pragma unroll
            for (int i = 0; i < 16; i++) {
                float v0 = ar[2*i], v1 = ar[2*i+1];
                unsigned hp = bfpack(v0, v1);
                float l0 = v0 - __int_as_float(hp << 16);
                float l1 = v1 - __int_as_float(hp & 0xffff0000u);
                unsigned lp = bfpack(l0, l1);
                int sw = SW128X(base + i * 4);
                *(unsigned*)(sb + sw) = hp;
                *(unsigned*)(sb + 16384 + sw) = lp;
            }
        }
        {
            int n = tid & 63, kb = (tid >> 6) * 16;
#pragma unroll
            for (int i = 0; i < 8; i++) {
                int k = k0 + kb + 2 * i;
                float v0 = W[(size_t)k * N + col0 + n];
                float v1 = W[(size_t)(k + 1) * N + col0 + n];
                unsigned hp = bfpack(v0, v1);
                float l0 = v0 - __int_as_float(hp << 16);
                float l1 = v1 - __int_as_float(hp & 0xffff0000u);
                unsigned lp = bfpack(l0, l1);
                int sw = SW128X(n * 128 + (kb + 2*i) * 2);
                *(unsigned*)(sb + 32768 + sw) = hp;
                *(unsigned*)(sb + 40960 + sw) = lp;
            }
        }
        __syncthreads();
#pragma unroll
        for (int ks = 0; ks < 4; ks++) {
            unsigned ah[4], al[4], bh[4][4], bl[4][4];
            unsigned ra = smb + SW128X(arow * 128 + (ks * 16 + acol) * 2);
            ldmx4(ah, ra); ldmx4(al, ra + 16384);
#pragma unroll
            for (int g = 0; g < 4; g++) {
                unsigned rb = smb + 32768 + SW128X((g * 16 + brow) * 128 + (ks * 16 + bcol) * 2);
                ldmx4(bh[g], rb); ldmx4(bl[g], rb + 8192);
            }
#pragma unroll
            for (int nt = 0; nt < 8; nt++) {
                const unsigned* bhp = &bh[nt >> 1][(nt & 1) * 2];
                const unsigned* blp = &bl[nt >> 1][(nt & 1) * 2];
                mmabf(acc[nt], ah, bhp);
                mmabf(acc[nt], ah, blp);
                mmabf(acc[nt], al, bhp);
            }
        }
    }
    int r = row0 + wid * 16 + (lane >> 2);
    int c = col0 + (lane & 3) * 2;
#pragma unroll
    for (int nt = 0; nt < 8; nt++) {
        Cc[(size_t)r * N + c + nt*8]       = acc[nt][0];
        Cc[(size_t)r * N + c + nt*8 + 1]   = acc[nt][1];
        Cc[(size_t)(r+8) * N + c + nt*8]   = acc[nt][2];
        Cc[(size_t)(r+8) * N + c + nt*8+1] = acc[nt][3];
    }
}

template<int C>
__global__ void k_knn(const float* __restrict__ x)
{
    extern __shared__ float s[];
    float* xs = s;
    float* ds = s + NPTS * (C + 1);
    const int b = blockIdx.x;
    for (int i = threadIdx.x; i < NPTS * C; i += 64) {
        int n = i / C, c = i - n * C;
        xs[n * (C + 1) + c] = x[(size_t)(b * NPTS + n) * C + c];
    }
    __syncthreads();
    const int n = threadIdx.x;
    for (int m = 0; m < NPTS; m++) {
        float acc = 0.f;
#pragma unroll 8
        for (int c = 0; c < C; c++) {
            float d = xs[n * (C + 1) + c] - xs[m * (C + 1) + c];
            acc = fmaf(d, d, acc);
        }
        ds[n * 65 + m] = acc;
    }
    for (int sIt = 0; sIt < KNBR + 1; sIt++) {
        float best = 3.4e38f; int bi = 0;
        for (int m = 0; m < NPTS; m++) {
            float v = ds[n * 65 + m];
            if (v < best) { best = v; bi = m; }
        }
        ds[n * 65 + bi] = 3.4e38f;
        if (sIt > 0) g_idx[(b * NPTS + n) * KNBR + sIt - 1] = bi;
    }
}

__global__ void k_wdiff(const float* __restrict__ w1, int C, int C1)
{
    int i = blockIdx.x * blockDim.x + threadIdx.x;
    if (i < C * C1) g_wd[i] = w1[i] - w1[C * C1 + i];
}
__global__ void k_zero_stats()
{
    g_sum[threadIdx.x] = 0.f; g_sumsq[threadIdx.x] = 0.f;
}
__global__ void k_colstats(const float* __restrict__ X, int M, int Ncol, int rpb)
{
    int c = threadIdx.x;
    int r0 = blockIdx.x * rpb, r1 = min(r0 + rpb, M);
    float s = 0.f, s2 = 0.f;
    for (int r = r0; r < r1; r++) {
        float v = X[(size_t)r * Ncol + c];
        s += v; s2 = fmaf(v, v, s2);
    }
    atomicAdd(&g_sum[c], s);
    atomicAdd(&g_sumsq[c], s2);
}
__global__ void k_edgestats(const float* __restrict__ p, const float* __restrict__ q, int C1)
{
    const int b = blockIdx.x;
    const int c = threadIdx.x;
    __shared__ int idxs[NPTS * KNBR];
    for (int i = threadIdx.x; i < NPTS * KNBR; i += blockDim.x)
        idxs[i] = g_idx[b * NPTS * KNBR + i];
    __syncthreads();
    float s = 0.f, s2 = 0.f;
    for (int n = 0; n < NPTS; n++) {
        float pv = p[(size_t)(b * NPTS + n) * C1 + c];
#pragma unroll
        for (int k = 0; k < KNBR; k++) {
            int j = idxs[n * KNBR + k];
            float v = pv + q[(size_t)(b * NPTS + j) * C1 + c];
            s += v; s2 = fmaf(v, v, s2);
        }
    }
    atomicAdd(&g_sum[c], s);
    atomicAdd(&g_sumsq[c], s2);
}
__global__ void k_finalize(const float* __restrict__ g, const float* __restrict__ bb,
                           int C, float invcnt)
{
    int c = threadIdx.x;
    if (c < C) {
        float m  = g_sum[c] * invcnt;
        float vv = g_sumsq[c] * invcnt - m * m;
        float sc = g[c] * rsqrtf(vv + EPSV);
        g_scale[c] = sc;
        g_shift[c] = bb[c] - m * sc;
    }
}
__global__ void k_bnlrelu(const float* __restrict__ X, float* __restrict__ Y,
                          int total, int mask)
{
    int i = blockIdx.x * blockDim.x + threadIdx.x;
    if (i < total) {
        int c = i & mask;
        float v = fmaf(X[i], g_scale[c], g_shift[c]);
        Y[i] = fmaxf(v, 0.2f * v);
    }
}
__global__ void k_maxfix(const float* __restrict__ raw, float* __restrict__ Y,
                         int total, int mask)
{
    int i = blockIdx.x * blockDim.x + threadIdx.x;
    if (i < total) {
        float v = raw[i];
        if (v < -3.0e38f) Y[i] = 0.f;
        else {
            int c = i & mask;
            float t = fmaf(v, g_scale[c], g_shift[c]);
            Y[i] = fmaxf(t, 0.2f * t);
        }
    }
}

// ---- HMMA edge GEMM2 + bn2 stats + scatter-max (256 threads, 8 warps) ----
template<int C1> struct Lay {
    static constexpr int IDX = 0;
    static constexpr int PT  = 4096;
    static constexpr int QT  = PT + C1*36;
    static constexpr int BHI = QT + C1*264;
    static constexpr int BLO = BHI + (C1/64)*8192;
    static constexpr int AHI = BLO + (C1/64)*8192;
    static constexpr int ALO = AHI + 16384;
    static constexpr int OM  = ALO + 16384;
    static constexpr int TOT = OM + 64*65*4;
};

template<int C1>
__global__ __launch_bounds__(256, 1) void k_hmma2(
    const float* __restrict__ p, const float* __restrict__ q,
    const float* __restrict__ w2, int C2, float* __restrict__ omg)
{
    using L = Lay<C1>;
    constexpr int KC = C1 / 64;
    extern __shared__ char sm[];
    const unsigned smb = sm_u32(sm);
    int*   idxs = (int*)(sm + L::IDX);
    float* p_t  = (float*)(sm + L::PT);
    float* q_t  = (float*)(sm + L::QT);
    float* om   = (float*)(sm + L::OM);
    const int b = blockIdx.x, cb = blockIdx.y * 64;
    const int tid = threadIdx.x, wid = tid >> 5, lane = tid & 31;

    for (int i = tid; i < 1024; i += 256) idxs[i] = g_idx[b * 1024 + i];
    for (int i = tid; i < 64 * C1; i += 256) {
        int j = i / C1, k = i - j * C1;
        q_t[k * 66 + j] = g_scale[k] * q[(size_t)(b * 64 + j) * C1 + k];
    }
    for (int i = tid; i < 64 * (C1 / 2); i += 256) {
        int n = i & 63, k0 = (i >> 6) * 2;
        float v0 = w2[(size_t)k0 * C2 + cb + n];
        float v1 = w2[(size_t)(k0 + 1) * C2 + cb + n];
        unsigned hp = bfpack(v0, v1);
        float l0 = v0 - __int_as_float(hp << 16);
        float l1 = v1 - __int_as_float(hp & 0xffff0000u);
        unsigned lp = bfpack(l0, l1);
        int sw = SW128X(n * 128 + (k0 & 63) * 2), tb = (k0 >> 6) * 8192;
        *(unsigned*)(sm + L::BHI + tb + sw) = hp;
        *(unsigned*)(sm + L::BLO + tb + sw) = lp;
    }
    const float NEGINF = __int_as_float(0xff800000);
    for (int i = tid; i < 64 * 65; i += 256) om[i] = NEGINF;

    float ls[16], lq[16];
#pragma unroll
    for (int s = 0; s < 16; s++) { ls[s] = 0.f; lq[s] = 0.f; }

    const int arow = wid * 16 + (lane & 15);
    const int acol = ((lane >> 4) & 1) * 8;
    const int brow = (lane & 7) + ((lane >> 4) & 1) * 8;
    const int bcol = ((lane >> 3) & 1) * 8;
    __syncthreads();

    for (int chunk = 0; chunk < 8; chunk++) {
        for (int i = tid; i < 8 * C1; i += 256) {
            int n = i / C1, k = i - n * C1;
            p_t[k * 9 + n] = fmaf(p[(size_t)(b * 64 + chunk * 8 + n) * C1 + k],
                                  g_scale[k], g_shift[k]);
        }
        float acc[8][4];
#pragma unroll
        for (int nt = 0; nt < 8; nt++)
#pragma unroll
            for (int r = 0; r < 4; r++) acc[nt][r] = 0.f;

        for (int kc = 0; kc < KC; kc++) {
            __syncthreads();
            {
                const int r = tid >> 1, hf = (tid & 1) * 16;
                const int n8 = (r >> 4) & 7;
                const int j = idxs[chunk * 128 + r];
                char* ah = sm + L::AHI;
                char* al = sm + L::ALO;
#pragma unroll
                for (int kp = 0; kp < 16; kp++) {
                    int k = kc * 64 + (hf + kp) * 2;
                    float f0 = p_t[k * 9 + n8]       + q_t[k * 66 + j];
                    float f1 = p_t[(k + 1) * 9 + n8] + q_t[(k + 1) * 66 + j];
                    f0 = fmaxf(f0, 0.2f * f0);
                    f1 = fmaxf(f1, 0.2f * f1);
                    unsigned hp = bfpack(f0, f1);
                    float l0 = f0 - __int_as_float(hp << 16);
                    float l1 = f1 - __int_as_float(hp & 0xffff0000u);
                    unsigned lp = bfpack(l0, l1);
                    int sw = SW128X(r * 128 + (hf + kp) * 4);
                    *(unsigned*)(ah + sw) = hp;
                    *(unsigned*)(al + sw) = lp;
                }
            }
            __syncthreads();
#pragma unroll
            for (int ks = 0; ks < 4; ks++) {
                unsigned ah[4], al[4], bh[4][4], bl[4][4];
                unsigned ra = smb + L::AHI + SW128X(arow * 128 + (ks * 16 + acol) * 2);
                ldmx4(ah, ra); ldmx4(al, ra + 16384);
#pragma unroll
                for (int g = 0; g < 4; g++) {
                    unsigned rb = smb + L::BHI + kc * 8192 +
                        SW128X((g * 16 + brow) * 128 + (ks * 16 + bcol) * 2);
                    ldmx4(bh[g], rb); ldmx4(bl[g], rb + KC * 8192);
                }
#pragma unroll
                for (int nt = 0; nt < 8; nt++) {
                    const unsigned* bhp = &bh[nt >> 1][(nt & 1) * 2];
                    const unsigned* blp = &bl[nt >> 1][(nt & 1) * 2];
                    mmabf(acc[nt], ah, bhp);
                    mmabf(acc[nt], ah, blp);
                    mmabf(acc[nt], al, bhp);
                }
            }
        }
        int e0 = chunk * 128 + wid * 16 + (lane >> 2);
        int ja = idxs[e0], jb = idxs[e0 + 8];
#pragma unroll
        for (int nt = 0; nt < 8; nt++) {
            int c0 = nt * 8 + (lane & 3) * 2;
            float y0 = acc[nt][0], y1 = acc[nt][1];
            float y2 = acc[nt][2], y3 = acc[nt][3];
            ls[nt*2]   += y0 + y2;
            lq[nt*2]    = fmaf(y0, y0, fmaf(y2, y2, lq[nt*2]));
            ls[nt*2+1] += y1 + y3;
            lq[nt*2+1]  = fmaf(y1, y1, fmaf(y3, y3, lq[nt*2+1]));
            float* oa = om + ja * 65 + c0;
            float* ob = om + jb * 65 + c0;
            if (y0 > oa[0]) atomicMaxFloat(oa,     y0);
            if (y1 > oa[1]) atomicMaxFloat(oa + 1, y1);
            if (y2 > ob[0]) atomicMaxFloat(ob,     y2);
            if (y3 > ob[1]) atomicMaxFloat(ob + 1, y3);
        }
    }
#pragma unroll
    for (int s = 0; s < 16; s++) {
#pragma unroll
        for (int o = 4; o < 32; o <<= 1) {
            ls[s] += __shfl_xor_sync(~0u, ls[s], o);
            lq[s] += __shfl_xor_sync(~0u, lq[s], o);
        }
    }
    if (lane < 4) {
#pragma unroll
        for (int s = 0; s < 16; s++) {
            int c = (s >> 1) * 8 + lane * 2 + (s & 1);
            atomicAdd(&g_sum[cb + c], ls[s]);
            atomicAdd(&g_sumsq[cb + c], lq[s]);
        }
    }
    __syncthreads();
    for (int i = tid; i < 64 * 64; i += 256) {
        int jj = i >> 6, c = i & 63;
        omg[(size_t)(b * 64 + jj) * C2 + cb + c] = om[jj * 65 + c];
    }
}

__global__ void k_pool()
{
    const int b = blockIdx.x;
    const int c = threadIdx.x;
    const float* src; int cc, Cs;
    if (c < 64)       { src = g_h1; cc = c;       Cs = 64; }
    else if (c < 192) { src = g_h2; cc = c - 64;  Cs = 128; }
    else              { src = g_h3; cc = c - 192; Cs = 256; }
    float s = 0.f, mx = -3.4e38f;
    for (int n = 0; n < NPTS; n++) {
        float v = src[(size_t)(b * NPTS + n) * Cs + cc];
        s += v; mx = fmaxf(mx, v);
    }
    g_pooled[b * 896 + c]       = s * (1.f / 64.f);
    g_pooled[b * 896 + 448 + c] = mx;
}

__global__ void k_head_final(const float* __restrict__ wc3, const float* __restrict__ bc3,
                             float* __restrict__ out)
{
    int i = blockIdx.x * blockDim.x + threadIdx.x;
    if (i < BATCH * 2) {
        int bb = i >> 1, o = i & 1;
        float s = 0.f;
#pragma unroll 8
        for (int c = 0; c < 256; c++)
            s = fmaf(g_z2[bb * 256 + c], wc3[c * 2 + o], s);
        out[i] = s + bc3[o];
    }
}

// ---------------- host side ----------------
static void run_conv(const float* xin, int C,
                     const float* w1, const float* g1, const float* b1,
                     const float* w2, const float* g2, const float* b2,
                     float* outh, int C1, int C2,
                     float* p, float* q, float* wd, float* maxraw,
                     int use_hgemm)
{
    if (C == 64) {
        size_t smk = (size_t)(NPTS * 65 * 2) * 4;
        cudaFuncSetAttribute(k_knn<64>, cudaFuncAttributeMaxDynamicSharedMemorySize, (int)smk);
        k_knn<64><<<BATCH, 64, smk>>>(xin);
    } else {
        size_t smk = (size_t)(NPTS * 129 + NPTS * 65) * 4;
        cudaFuncSetAttribute(k_knn<128>, cudaFuncAttributeMaxDynamicSharedMemorySize, (int)smk);
        k_knn<128><<<BATCH, 64, smk>>>(xin);
    }
    k_wdiff<<<(C * C1 + 255) / 256, 256>>>(w1, C, C1);
    if (use_hgemm) {
        k_hgemm<<<dim3(C1 / 64, BNTOT / 128), 256>>>(xin, w1 + (size_t)C * C1, p, BNTOT, C, C1);
        k_hgemm<<<dim3(C1 / 64, BNTOT / 128), 256>>>(xin, wd, q, BNTOT, C, C1);
    } else {
        k_gemm<<<dim3(C1 / 64, BNTOT / 64), 256>>>(xin, w1 + (size_t)C * C1, p, BNTOT, C, C1);
        k_gemm<<<dim3(C1 / 64, BNTOT / 64), 256>>>(xin, wd, q, BNTOT, C, C1);
    }
    k_zero_stats<<<1, 512>>>();
    k_edgestats<<<BATCH, C1>>>(p, q, C1);
    k_finalize<<<1, 512>>>(g1, b1, C1, 1.f / (float)NEDGE);
    k_zero_stats<<<1, 512>>>();
    dim3 grid2(BATCH, C2 / 64);
    if (C1 == 64) {
        cudaFuncSetAttribute(k_hmma2<64>, cudaFuncAttributeMaxDynamicSharedMemorySize, Lay<64>::TOT);
        k_hmma2<64><<<grid2, 256, Lay<64>::TOT>>>(p, q, w2, C2, maxraw);
    } else if (C1 == 128) {
        cudaFuncSetAttribute(k_hmma2<128>, cudaFuncAttributeMaxDynamicSharedMemorySize, Lay<128>::TOT);
        k_hmma2<128><<<grid2, 256, Lay<128>::TOT>>>(p, q, w2, C2, maxraw);
    } else {
        cudaFuncSetAttribute(k_hmma2<256>, cudaFuncAttributeMaxDynamicSharedMemorySize, Lay<256>::TOT);
        k_hmma2<256><<<grid2, 256, Lay<256>::TOT>>>(p, q, w2, C2, maxraw);
    }
    k_finalize<<<1, 512>>>(g2, b2, C2, 1.f / (float)NEDGE);
    k_maxfix<<<(BNTOT * C2) / 256, 256>>>(maxraw, outh, BNTOT * C2, C2 - 1);
}

extern "C" void kernel_launch(void* const* d_in, const int* in_sizes, int n_in,
                              void* d_out, int out_size)
{
    const float* x    = (const float*)d_in[0];
    const float* w_in = (const float*)d_in[2];
    const float* g_in = (const float*)d_in[3];
    const float* b_in = (const float*)d_in[4];
    const float* w1a  = (const float*)d_in[5];
    const float* g1a  = (const float*)d_in[6];
    const float* b1a  = (const float*)d_in[7];
    const float* w1b  = (const float*)d_in[8];
    const float* g1b  = (const float*)d_in[9];
    const float* b1b  = (const float*)d_in[10];
    const float* w2a  = (const float*)d_in[11];
    const float* g2a  = (const float*)d_in[12];
    const float* b2a  = (const float*)d_in[13];
    const float* w2b  = (const float*)d_in[14];
    const float* g2b  = (const float*)d_in[15];
    const float* b2b  = (const float*)d_in[16];
    const float* w3a  = (const float*)d_in[17];
    const float* g3a  = (const float*)d_in[18];
    const float* b3a  = (const float*)d_in[19];
    const float* w3b  = (const float*)d_in[20];
    const float* g3b  = (const float*)d_in[21];
    const float* b3b  = (const float*)d_in[22];
    const float* wc1  = (const float*)d_in[23];
    const float* gc1  = (const float*)d_in[24];
    const float* bc1  = (const float*)d_in[25];
    const float* wc2  = (const float*)d_in[26];
    const float* gc2  = (const float*)d_in[27];
    const float* bc2  = (const float*)d_in[28];
    const float* wc3  = (const float*)d_in[29];
    const float* bc3  = (const float*)d_in[30];
    float* out = (float*)d_out;

    float *h0, *h1, *h2, *h3, *p, *q, *wd, *mr, *pooled, *z1, *z2;
    cudaGetSymbolAddress((void**)&h0, g_h0);
    cudaGetSymbolAddress((void**)&h1, g_h1);
    cudaGetSymbolAddress((void**)&h2, g_h2);
    cudaGetSymbolAddress((void**)&h3, g_h3);
    cudaGetSymbolAddress((void**)&p,  g_p);
    cudaGetSymbolAddress((void**)&q,  g_q);
    cudaGetSymbolAddress((void**)&wd, g_wd);
    cudaGetSymbolAddress((void**)&mr, g_maxraw);
    cudaGetSymbolAddress((void**)&pooled, g_pooled);
    cudaGetSymbolAddress((void**)&z1, g_z1);
    cudaGetSymbolAddress((void**)&z2, g_z2);

    k_gemm<<<dim3(1, BNTOT / 64), 256>>>(x, w_in, h0, BNTOT, 6, 64);
    k_zero_stats<<<1, 512>>>();
    k_colstats<<<256, 64>>>(h0, BNTOT, 64, BNTOT / 256);
    k_finalize<<<1, 512>>>(g_in, b_in, 64, 1.f / (float)BNTOT);
    k_bnlrelu<<<(BNTOT * 64) / 256, 256>>>(h0, h0, BNTOT * 64, 63);

    run_conv(h0, 64,  w1a, g1a, b1a, w1b, g1b, b1b, h1, 64, 64,  p, q, wd, mr, 0);
    run_conv(h1, 64,  w2a, g2a, b2a, w2b, g2b, b2b, h2, 128, 128, p, q, wd, mr, 0);
    run_conv(h2, 128, w3a, g3a, b3a, w3b, g3b, b3b, h3, 256, 256, p, q, wd, mr, 1);

    k_pool<<<BATCH, 448>>>();

    k_gemm<<<dim3(8, BATCH / 64), 256>>>(pooled, wc1, z1, BATCH, 896, 512);
    k_zero_stats<<<1, 512>>>();
    k_colstats<<<8, 512>>>(z1, BATCH, 512, BATCH / 8);
    k_finalize<<<1, 512>>>(gc1, bc1, 512, 1.f / (float)BATCH);
    k_bnlrelu<<<(BATCH * 512) / 256, 256>>>(z1, z1, BATCH * 512, 511);

    k_gemm<<<dim3(4, BATCH / 64), 256>>>(z1, wc2, z2, BATCH, 512, 256);
    k_zero_stats<<<1, 512>>>();
    k_colstats<<<8, 256>>>(z2, BATCH, 256, BATCH / 8);
    k_finalize<<<1, 512>>>(gc2, bc2, 256, 1.f / (float)BATCH);
    k_bnlrelu<<<(BATCH * 256) / 256, 256>>>(z2, z2, BATCH * 256, 255);

    k_head_final<<<4, 256>>>(wc3, bc3, out);
}